// round 17
// baseline (speedup 1.0000x reference)
#include <cuda_runtime.h>
#include <cuda_fp16.h>
#include <cstdint>
#include <math.h>

// Problem constants (fixed by setup_inputs)
#define N_PTS   50000
#define TILE_E  128                      // edges per CTA (4 output rows)
#define ROWS_PER_CTA 4
#define NUM_CTAS (N_PTS / ROWS_PER_CTA)  // 12500

// Precomputed first-layer projections, both fp16 (validated error budget).
__device__ __half g_yWa16[N_PTS * 64];   // fp16(y @ W0[0:3,:])   gathered
__device__ __half g_yWb16[N_PTS * 64];   // fp16(y @ W0[3:6,:]+b0) warp-uniform
__device__ __half g_f16[N_PTS * 64];     // fp16(f_y)             gathered

// Pre-transposed W1 (fp16) in the exact XOR-swizzled smem byte layout:
// row n (128 B), granule (k>>3)^(n&7), byte (k&7)*2.
__device__ __align__(16) unsigned char g_Bt[64 * 128];

// ---- shared memory layout (bytes). 128 B rows + XOR granule swizzle ----
#define SM_A    0                        // 128 x 128 B (fp16 H tile)
#define SM_B    (128 * 128)              // 64 x 128 B (fp16 W1^T)
#define SM_F    (SM_B + 64 * 128)        // 128 x 128 B (fp16 f rows, swizzled)
#define SM_TOTAL (SM_F + 128 * 128)      // 40960 B -> 5 CTAs/SM

__device__ __forceinline__ uint32_t smem_u32(const void* p) {
    uint32_t a;
    asm("{ .reg .u64 t; cvta.to.shared.u64 t, %1; cvt.u32.u64 %0, t; }"
        : "=r"(a) : "l"(p));
    return a;
}
__device__ __forceinline__ void ldsm4(uint32_t r[4], uint32_t addr) {
    asm volatile("ldmatrix.sync.aligned.m8n8.x4.shared.b16 {%0,%1,%2,%3}, [%4];"
                 : "=r"(r[0]), "=r"(r[1]), "=r"(r[2]), "=r"(r[3]) : "r"(addr));
}
__device__ __forceinline__ void mma16816(float c[4], const uint32_t a[4],
                                         uint32_t b0, uint32_t b1) {
    asm volatile(
        "mma.sync.aligned.m16n8k16.row.col.f32.f16.f16.f32 "
        "{%0,%1,%2,%3}, {%4,%5,%6,%7}, {%8,%9}, {%0,%1,%2,%3};"
        : "+f"(c[0]), "+f"(c[1]), "+f"(c[2]), "+f"(c[3])
        : "r"(a[0]), "r"(a[1]), "r"(a[2]), "r"(a[3]), "r"(b0), "r"(b1));
}

// Fast GELU: tanh form via hardware tanh.approx.f32 (5 flops + 1 MUFU).
__device__ __forceinline__ float gelu(float x) {
    float x2 = x * x;
    float t1 = fmaf(0.03567740814f, x2, 0.7978845608f);
    float u  = x * t1;
    float th;
    asm("tanh.approx.f32 %0, %1;" : "=f"(th) : "f"(u));
    float hx = 0.5f * x;
    return fmaf(hx, th, hx);
}

// ======================= prep kernel =======================
// blocks [0,3125): yWa/yWb fp16;  block 3125: W1 fp16 swizzle;
// blocks [3126,4689): f_y -> fp16 copy.
#define PREP_GRID 4689
__global__ __launch_bounds__(256)
void precompute_kernel(const float* __restrict__ y,
                       const float* __restrict__ W0,
                       const float* __restrict__ b0,
                       const float* __restrict__ W1,
                       const float* __restrict__ f_y)
{
    if (blockIdx.x == 3125) {
        #pragma unroll
        for (int it = 0; it < 16; it++) {
            int idx = threadIdx.x + it * 256;
            int k = idx >> 6, n = idx & 63;
            float w = __ldg(&W1[idx]);
            uint32_t off = (uint32_t)(n * 128 + ((((k >> 3) ^ (n & 7)) << 4)
                                                 | ((k & 7) * 2)));
            *(__half*)(&g_Bt[off]) = __float2half_rn(w);
        }
        return;
    }
    if (blockIdx.x > 3125) {
        int base = ((blockIdx.x - 3126) * 256 + threadIdx.x) * 8;
        if (base < N_PTS * 64) {
            float4 v0 = *(const float4*)&f_y[base];
            float4 v1 = *(const float4*)&f_y[base + 4];
            __half2 o0 = __floats2half2_rn(v0.x, v0.y);
            __half2 o1 = __floats2half2_rn(v0.z, v0.w);
            __half2 o2 = __floats2half2_rn(v1.x, v1.y);
            __half2 o3 = __floats2half2_rn(v1.z, v1.w);
            uint4 pk = make_uint4(*(uint32_t*)&o0, *(uint32_t*)&o1,
                                  *(uint32_t*)&o2, *(uint32_t*)&o3);
            *(uint4*)&g_f16[base] = pk;
        }
        return;
    }
    int idx = blockIdx.x * blockDim.x + threadIdx.x;   // n*16 + c4
    int n = idx >> 4, c4 = (idx & 15) << 2;
    float y0 = __ldg(&y[n * 3 + 0]);
    float y1 = __ldg(&y[n * 3 + 1]);
    float y2 = __ldg(&y[n * 3 + 2]);
    float4 w0 = *(const float4*)&W0[0 * 64 + c4];
    float4 w1 = *(const float4*)&W0[1 * 64 + c4];
    float4 w2 = *(const float4*)&W0[2 * 64 + c4];
    float4 w3 = *(const float4*)&W0[3 * 64 + c4];
    float4 w4 = *(const float4*)&W0[4 * 64 + c4];
    float4 w5 = *(const float4*)&W0[5 * 64 + c4];
    float4 bb = *(const float4*)&b0[c4];
    float ax = y0 * w0.x + y1 * w1.x + y2 * w2.x;
    float ay = y0 * w0.y + y1 * w1.y + y2 * w2.y;
    float az = y0 * w0.z + y1 * w1.z + y2 * w2.z;
    float aw = y0 * w0.w + y1 * w1.w + y2 * w2.w;
    float bx = y0 * w3.x + y1 * w4.x + y2 * w5.x + bb.x;
    float by = y0 * w3.y + y1 * w4.y + y2 * w5.y + bb.y;
    float bz = y0 * w3.z + y1 * w4.z + y2 * w5.z + bb.z;
    float bw = y0 * w3.w + y1 * w4.w + y2 * w5.w + bb.w;
    __half2 a01 = __floats2half2_rn(ax, ay);
    __half2 a23 = __floats2half2_rn(az, aw);
    __half2 b01 = __floats2half2_rn(bx, by);
    __half2 b23 = __floats2half2_rn(bz, bw);
    *(uint2*)&g_yWa16[n * 64 + c4] = make_uint2(*(uint32_t*)&a01,
                                                *(uint32_t*)&a23);
    *(uint2*)&g_yWb16[n * 64 + c4] = make_uint2(*(uint32_t*)&b01,
                                                *(uint32_t*)&b23);
}

// ======================= main kernel =======================
// Two independent half-CTA pipelines (warps 0-3 / 4-7). Warp q=(mblk,nhalf)
// owns M=32 edges x N=32 channels. A = fp16 H tile, B = fp16 W1^T, single
// MMA pass, fp32 accum. f rows flow global->smem via 8B cp.async (no RF
// round-trip) into a swizzled tile; epilogue reads them via conflict-free
// LDS. One named barrier per half total.
__global__ __launch_bounds__(256, 5)
void integral_mma_kernel(const float* __restrict__ b1,
                         const int*   __restrict__ nbr,
                         float*       __restrict__ out)
{
    extern __shared__ char smem[];
    const uint32_t sb = smem_u32(smem);
    const int tid  = threadIdx.x;
    const int wid  = tid >> 5;            // 0..7
    const int lane = tid & 31;
    const int h    = tid >> 7;            // half id
    const int tl   = tid & 127;           // thread-in-half
    const int i0   = blockIdx.x * ROWS_PER_CTA;
    const int ebase = blockIdx.x * TILE_E;

    // ---- B tile via cp.async (8 KB; each half copies all -- duplicate
    //      writes are benign and keep the halves independent) ----
    #pragma unroll
    for (int it = 0; it < 4; it++) {
        int idx = tl + it * 128;                   // 0..511 (16B units)
        uint32_t off = (uint32_t)(idx * 16);
        uint32_t saddr = sb + SM_B + off;
        const void* g = &g_Bt[off];
        asm volatile("cp.async.cg.shared.global [%0], [%1], 16;"
                     :: "r"(saddr), "l"(g));
    }

    // ---- A + F tiles (this half's 64 edges):
    //      A[e] = fp16(gelu(fp16 yWa[j] + fp16 yWb[i])), swizzled STS.
    //      F[e] row chunk flows via 8B cp.async into the same swizzle. ----
    {
        const uint2* yWa2 = (const uint2*)g_yWa16;   // 4 halfs per entry
        const uint2* yWb2 = (const uint2*)g_yWb16;
        const int p4 = tl & 15;                    // 4-channel group index
        uint2 bAu = __ldg(&yWb2[(i0 + h * 2 + 0) * 16 + p4]);
        uint2 bBu = __ldg(&yWb2[(i0 + h * 2 + 1) * 16 + p4]);
        float2 bA01 = __half22float2(*(__half2*)&bAu.x);
        float2 bA23 = __half22float2(*(__half2*)&bAu.y);
        float2 bB01 = __half22float2(*(__half2*)&bBu.x);
        float2 bB23 = __half22float2(*(__half2*)&bBu.y);
        #pragma unroll
        for (int it = 0; it < 8; it++) {
            int el = (tl >> 4) + it * 8;           // 0..63 (it<4 -> el<32)
            int e  = h * 64 + el;                  // smem row
            int j  = __ldg(&nbr[ebase + e]);
            uint32_t off = (uint32_t)(e * 128 + ((((p4 >> 1) ^ (e & 7)) << 4)
                                                 | ((p4 & 1) << 3)));
            // f chunk: global->smem, no register round-trip
            const void* fg = &g_f16[j * 64 + p4 * 4];
            asm volatile("cp.async.ca.shared.global [%0], [%1], 8;"
                         :: "r"(sb + SM_F + off), "l"(fg));
            uint2 av = __ldg(&yWa2[j * 16 + p4]);
            float2 a01 = __half22float2(*(__half2*)&av.x);
            float2 a23 = __half22float2(*(__half2*)&av.y);
            float x0, x1, x2, x3;
            if (it < 4) {
                x0 = gelu(a01.x + bA01.x);
                x1 = gelu(a01.y + bA01.y);
                x2 = gelu(a23.x + bA23.x);
                x3 = gelu(a23.y + bA23.y);
            } else {
                x0 = gelu(a01.x + bB01.x);
                x1 = gelu(a01.y + bB01.y);
                x2 = gelu(a23.x + bB23.x);
                x3 = gelu(a23.y + bB23.y);
            }
            __half2 h01 = __floats2half2_rn(x0, x1);
            __half2 h23 = __floats2half2_rn(x2, x3);
            *(uint2*)(smem + SM_A + off) =
                make_uint2(*(uint32_t*)&h01, *(uint32_t*)&h23);
        }
    }
    asm volatile("cp.async.commit_group;" ::: "memory");
    asm volatile("cp.async.wait_group 0;" ::: "memory");
    asm volatile("bar.sync %0, 128;" :: "r"(1 + h) : "memory");

    // ---- warp role: mblk = which 32 edges (row), nhalf = channel half ----
    const int q     = wid & 3;
    const int mblk  = q & 1;
    const int nhalf = q >> 1;
    const int n0    = nhalf * 32;
    const int wEdge = h * 64 + mblk * 32;          // warp's first A row

    // ---- GEMM: M=32 (2 mtiles), N=32 (4 ntiles), single pass, fp32 accum ----
    float acc[2][4][4];
    #pragma unroll
    for (int mt = 0; mt < 2; mt++)
        #pragma unroll
        for (int nt = 0; nt < 4; nt++)
            #pragma unroll
            for (int r = 0; r < 4; r++) acc[mt][nt][r] = 0.0f;

    const uint32_t swz  = (uint32_t)(lane & 7);
    const uint32_t ag0  = (uint32_t)(lane >> 4);
    const uint32_t brow = (uint32_t)((lane >> 4) * 8 + (lane & 7));
    const uint32_t bg0  = (uint32_t)((lane >> 3) & 1);

    #pragma unroll
    for (int ks = 0; ks < 4; ks++) {
        const uint32_t agr = ((ag0 + 2 * ks) ^ swz) << 4;
        const uint32_t bgr = ((bg0 + 2 * ks) ^ swz) << 4;
        uint32_t ah[2][4];
        #pragma unroll
        for (int mt = 0; mt < 2; mt++) {
            const uint32_t aoff =
                (uint32_t)(wEdge + mt * 16 + (lane & 15)) * 128 + agr;
            ldsm4(ah[mt], sb + SM_A + aoff);
        }
        #pragma unroll
        for (int np = 0; np < 2; np++) {
            const uint32_t boff = (uint32_t)(n0 + np * 16 + brow) * 128 + bgr;
            uint32_t bf[4];
            ldsm4(bf, sb + SM_B + boff);
            #pragma unroll
            for (int s = 0; s < 2; s++) {
                int nt = np * 2 + s;
                #pragma unroll
                for (int mt = 0; mt < 2; mt++)
                    mma16816(acc[mt][nt], ah[mt], bf[s * 2], bf[s * 2 + 1]);
            }
        }
    }

    // ---- epilogue: full row mean in-warp; f from swizzled smem (LDS is
    //      conflict-free: 8 rows span e&7=0..7 -> granules hit all banks). ----
    float ps[4][2];
    #pragma unroll
    for (int nt = 0; nt < 4; nt++) { ps[nt][0] = 0.0f; ps[nt][1] = 0.0f; }

    float2 bvr[4];
    #pragma unroll
    for (int nt = 0; nt < 4; nt++)
        bvr[nt] = __ldg((const float2*)(b1 + n0 + nt * 8 + (lane & 3) * 2));

    #pragma unroll
    for (int mt = 0; mt < 2; mt++)
        #pragma unroll
        for (int rg = 0; rg < 2; rg++) {
            int e = wEdge + mt * 16 + rg * 8 + (lane >> 2);
            #pragma unroll
            for (int nt = 0; nt < 4; nt++) {
                uint32_t gran = (uint32_t)(nhalf * 4 + nt) ^ (uint32_t)(e & 7);
                uint32_t faddr = sb + SM_F + (uint32_t)e * 128
                               + (gran << 4) + ((lane & 3) << 2);
                uint32_t fraw;
                asm volatile("ld.shared.b32 %0, [%1];" : "=r"(fraw) : "r"(faddr));
                float2 fv = __half22float2(*(__half2*)&fraw);
                ps[nt][0] += (acc[mt][nt][rg * 2 + 0] + bvr[nt].x) * fv.x;
                ps[nt][1] += (acc[mt][nt][rg * 2 + 1] + bvr[nt].y) * fv.y;
            }
        }

    #pragma unroll
    for (int nt = 0; nt < 4; nt++)
        #pragma unroll
        for (int hh = 0; hh < 2; hh++) {
            float v = ps[nt][hh];
            v += __shfl_xor_sync(0xffffffffu, v, 4);
            v += __shfl_xor_sync(0xffffffffu, v, 8);
            v += __shfl_xor_sync(0xffffffffu, v, 16);
            ps[nt][hh] = v;
        }

    // ---- write mean: warp's row, its 32-channel half; lanes 0-3 ----
    if (lane < 4) {
        float* orow = out + (i0 + h * 2 + mblk) * 64 + n0;
        #pragma unroll
        for (int nt = 0; nt < 4; nt++) {
            float2 v = make_float2(ps[nt][0] * (1.0f / 32.0f),
                                   ps[nt][1] * (1.0f / 32.0f));
            *(float2*)(orow + nt * 8 + lane * 2) = v;
        }
    }
}

extern "C" void kernel_launch(void* const* d_in, const int* in_sizes, int n_in,
                              void* d_out, int out_size)
{
    const float* y       = (const float*)d_in[0];   // [N,3]
    const float* f_y     = (const float*)d_in[1];   // [N,64]
    const float* W0      = (const float*)d_in[2];   // [6,64]
    const float* b0      = (const float*)d_in[3];   // [64]
    const float* W1      = (const float*)d_in[4];   // [64,64]
    const float* b1      = (const float*)d_in[5];   // [64]
    const int*   nbr_idx = (const int*)d_in[6];     // [E]
    float* out = (float*)d_out;                     // [N,64]

    cudaFuncSetAttribute(integral_mma_kernel,
                         cudaFuncAttributeMaxDynamicSharedMemorySize, SM_TOTAL);
    precompute_kernel<<<PREP_GRID, 256>>>(y, W0, b0, W1, f_y);
    integral_mma_kernel<<<NUM_CTAS, 256, SM_TOTAL>>>(b1, nbr_idx, out);
}